// round 5
// baseline (speedup 1.0000x reference)
#include <cuda_runtime.h>

#define BB 2
#define SS 2048
#define DD 128
#define HH 8
#define EPSF 1e-10f
#define FULLM 0xffffffffu
#define TTBLK 64            // phase-1 blocks (4096 rows, 8 thr/row, 512 thr/blk)
#define NROWS (BB * HH * SS)   // 32768 output rows

// Scratch (allocation-free rule: __device__ globals; zero-init at load)
__device__ int      g_tt[BB * SS];
__device__ int2     g_lohi[BB * SS];
__device__ unsigned g_cnt = 0;

// ---------------------------------------------------------------------------
// Kernel Z: blocks 0..63 = phase-1 (tt + suffix-min scan -> g_lohi).
//           blocks 64..  = stream suffix zeros (j > s) for one row each.
// No block waits on another: kernel boundary syncs Z -> P.
// ---------------------------------------------------------------------------
__global__ void __launch_bounds__(512) k_zero(const float* __restrict__ x,
                                              const float* __restrict__ gu,
                                              const float* __restrict__ W,
                                              const float* __restrict__ bias,
                                              float4* __restrict__ out) {
    const int tid = threadIdx.x;
    const int bid = blockIdx.x;

    if (bid >= TTBLK) {
        // ---------------- suffix-zero writer ----------------
        int row  = bid - TTBLK;          // 0..32767
        int s    = row & (SS - 1);
        int qdiag = s >> 2;
        if (tid > qdiag) {
            float4* orow = out + (size_t)row * (SS / 4);
            __stcs(&orow[tid], make_float4(0.f, 0.f, 0.f, 0.f));
        }
        return;
    }

    // ---------------- phase-1: token types ----------------
    __shared__ int sh_last;
    __shared__ int sh_wmin[16];
    __shared__ int sh_wsuf[16];

    {
        int gid = bid * 512 + tid;
        int row = gid >> 3;              // 0..4095 = b*S + s
        int r   = gid & 7;

        const float4* xr = reinterpret_cast<const float4*>(x + (size_t)row * DD);
        const float4* W4 = reinterpret_cast<const float4*>(W);

        float4 xv[4];
        #pragma unroll
        for (int i = 0; i < 4; i++) xv[i] = xr[r * 4 + i];

        float a0 = 0.f, a1 = 0.f, a2 = 0.f;
        #pragma unroll
        for (int i = 0; i < 4; i++) {
            int c = r * 4 + i;
            float4 w0 = W4[c];
            float4 w1 = W4[32 + c];
            float4 w2 = W4[64 + c];
            a0 += xv[i].x * w0.x + xv[i].y * w0.y + xv[i].z * w0.z + xv[i].w * w0.w;
            a1 += xv[i].x * w1.x + xv[i].y * w1.y + xv[i].z * w1.z + xv[i].w * w1.w;
            a2 += xv[i].x * w2.x + xv[i].y * w2.y + xv[i].z * w2.z + xv[i].w * w2.w;
        }
        #pragma unroll
        for (int off = 4; off; off >>= 1) {
            a0 += __shfl_xor_sync(FULLM, a0, off);
            a1 += __shfl_xor_sync(FULLM, a1, off);
            a2 += __shfl_xor_sync(FULLM, a2, off);
        }
        if (r == 0) {
            const float* gr = gu + (size_t)row * 3;
            float g0 = -logf(-logf(gr[0] + EPSF) + EPSF);
            float g1 = -logf(-logf(gr[1] + EPSF) + EPSF);
            float g2 = -logf(-logf(gr[2] + EPSF) + EPSF);
            float s0 = a0 + bias[0] + g0;
            float s1 = a1 + bias[1] + g1;
            float s2 = a2 + bias[2] + g2;
            int tt = 0; float best = s0;
            if (s1 > best) { best = s1; tt = 1; }   // first-max tie-break
            if (s2 > best) { best = s2; tt = 2; }
            g_tt[row] = tt;
        }
    }
    __syncthreads();
    if (tid == 0) {
        __threadfence();                              // release g_tt
        sh_last = (atomicAdd(&g_cnt, 1u) == TTBLK - 1);
    }
    __syncthreads();
    if (!sh_last) return;

    // ---------------- last block: suffix-min scan, publish (lo,hi) ----------
    __threadfence();                                  // acquire all g_tt
    int lane = tid & 31, wid = tid >> 5;              // 16 warps
    for (int b = 0; b < BB; b++) {
        __syncthreads();                              // shared reuse guard
        int base = b * SS + tid * 4;                  // 4 elems/thread
        int t0 = g_tt[base + 0], t1 = g_tt[base + 1];
        int t2 = g_tt[base + 2], t3 = g_tt[base + 3];
        int j0 = tid * 4;
        int e0 = (t0 == 0) ? j0     : SS;
        int e1 = (t1 == 0) ? j0 + 1 : SS;
        int e2 = (t2 == 0) ? j0 + 2 : SS;
        int e3 = (t3 == 0) ? j0 + 3 : SS;
        int m  = min(min(e0, e1), min(e2, e3));

        // inclusive suffix-min within warp (lanes ascend with index)
        int inc = m;
        #pragma unroll
        for (int off = 1; off < 32; off <<= 1) {
            int v = __shfl_down_sync(FULLM, inc, off);
            if (lane + off < 32) inc = min(inc, v);
        }
        int excl = __shfl_down_sync(FULLM, inc, 1);
        if (lane == 31) excl = SS;

        if (lane == 0) sh_wmin[wid] = inc;
        __syncthreads();
        if (wid == 0) {
            int wm = (lane < 16) ? sh_wmin[lane] : SS;
            int winc = wm;
            #pragma unroll
            for (int off = 1; off < 16; off <<= 1)
                winc = min(winc, __shfl_down_sync(FULLM, winc, off));
            int wex = __shfl_down_sync(FULLM, winc, 1);  // lane15 gets lane16's SS
            if (lane < 16) sh_wsuf[lane] = wex;
        }
        __syncthreads();
        int after = min(excl, sh_wsuf[wid]);          // min over idx > 4t+3

        int run = after;
        int ng3 = run; run = min(run, e3);
        int ng2 = run; run = min(run, e2);
        int ng1 = run; run = min(run, e1);
        int ng0 = run;

        int2 lh;
        #define EMIT(ii, tt_, ng_)                                  \
            { int j = j0 + ii; lh.x = 0; lh.y = j;                  \
              if (tt_ == 1)      { lh.x = j; lh.y = j; }            \
              else if (tt_ == 2) { lh.y = min(j, ng_); }            \
              g_lohi[base + ii] = lh; }
        EMIT(0, t0, ng0); EMIT(1, t1, ng1);
        EMIT(2, t2, ng2); EMIT(3, t3, ng3);
        #undef EMIT
    }
    __syncthreads();
    if (tid == 0) g_cnt = 0;            // reset for next graph replay
}

// ---------------------------------------------------------------------------
// Kernel P: write the causal prefix (j <= s) for each row from g_lohi.
// ---------------------------------------------------------------------------
__global__ void __launch_bounds__(512) k_prefix(float4* __restrict__ out) {
    int row = blockIdx.x;               // over B*H*S = 32768
    int s   = row & (SS - 1);
    int b   = row >> 14;                // / (H*S)
    int qdiag = s >> 2;
    int q = threadIdx.x;
    if (q > qdiag) return;

    int2 lh = g_lohi[b * SS + s];       // hi <= s always, so j > s -> 0 handled
    float4* orow = out + (size_t)row * (SS / 4);
    int j = q << 2;
    float4 v;
    v.x = (j     >= lh.x && j     <= lh.y) ? 1.0f : 0.0f;
    v.y = (j + 1 >= lh.x && j + 1 <= lh.y) ? 1.0f : 0.0f;
    v.z = (j + 2 >= lh.x && j + 2 <= lh.y) ? 1.0f : 0.0f;
    v.w = (j + 3 >= lh.x && j + 3 <= lh.y) ? 1.0f : 0.0f;
    __stcs(&orow[q], v);
}

extern "C" void kernel_launch(void* const* d_in, const int* in_sizes, int n_in,
                              void* d_out, int out_size) {
    const float* x    = (const float*)d_in[0];  // input_tensor (B,S,D)
    // d_in[1] = token_types (unused by reference)
    const float* gu   = (const float*)d_in[2];  // gumbel_u (B,S,3)
    const float* W    = (const float*)d_in[3];  // (3,D)
    const float* bias = (const float*)d_in[4];  // (3,)
    float4* out = (float4*)d_out;

    k_zero<<<TTBLK + NROWS, 512>>>(x, gu, W, bias, out);
    k_prefix<<<NROWS, 512>>>(out);
}

// round 7
// speedup vs baseline: 1.1307x; 1.1307x over previous
#include <cuda_runtime.h>

#define BB 2
#define SS 2048
#define DD 128
#define HH 8
#define EPSF 1e-10f
#define FULLM 0xffffffffu
#define TTBLK 64                 // phase-1 blocks (4096 rows, 8 thr/row, 512 thr/blk)
#define NPAIR (BB * HH * SS / 2) // 16384 complementary row pairs
#define QROW  (SS / 4)           // 512 float4 per row

// Scratch (allocation-free rule: __device__ globals; zero-init at load)
__device__ int      g_tt[BB * SS];
__device__ int2     g_lohi[BB * SS];
__device__ unsigned g_cnt = 0;

// ---------------------------------------------------------------------------
// Kernel Z: blocks 0..63 = phase-1 (tt + suffix-min scan -> g_lohi).
//           blocks 64..  = suffix zeros for one complementary row pair
//                          (s, 2047-s): exactly 511 float4s, all threads busy.
// ---------------------------------------------------------------------------
__global__ void __launch_bounds__(512) k_zero(const float* __restrict__ x,
                                              const float* __restrict__ gu,
                                              const float* __restrict__ W,
                                              const float* __restrict__ bias,
                                              float4* __restrict__ out) {
    const int tid = threadIdx.x;
    const int bid = blockIdx.x;

    if (bid >= TTBLK) {
        // ---------------- balanced suffix-zero writer ----------------
        int zb = bid - TTBLK;            // 0..16383
        int bh = zb >> 10;               // (b*8 + h)
        int a  = zb & 1023;              // s1 = a, s2 = 2047 - a
        int c  = a >> 2;                 // qdiag of row1; qdiag2 = 511 - c
        size_t base1 = (size_t)(bh * SS + a)        * QROW;
        size_t base2 = (size_t)(bh * SS + (SS-1-a)) * QROW;
        float4 z = make_float4(0.f, 0.f, 0.f, 0.f);
        int nz1 = 511 - c;               // zero float4s in row1
        if (tid < 511) {
            if (tid < nz1) __stcs(&out[base1 + c + 1 + tid], z);
            else           __stcs(&out[base2 + tid + 1], z);
        }
        return;
    }

    // ---------------- phase-1: token types ----------------
    __shared__ int sh_last;
    __shared__ int sh_wmin[16];
    __shared__ int sh_wsuf[16];

    {
        int gid = bid * 512 + tid;
        int row = gid >> 3;              // 0..4095 = b*S + s
        int r   = gid & 7;

        const float4* xr = reinterpret_cast<const float4*>(x + (size_t)row * DD);
        const float4* W4 = reinterpret_cast<const float4*>(W);

        float4 xv[4];
        #pragma unroll
        for (int i = 0; i < 4; i++) xv[i] = xr[r * 4 + i];

        float a0 = 0.f, a1 = 0.f, a2 = 0.f;
        #pragma unroll
        for (int i = 0; i < 4; i++) {
            int cc = r * 4 + i;
            float4 w0 = W4[cc];
            float4 w1 = W4[32 + cc];
            float4 w2 = W4[64 + cc];
            a0 += xv[i].x * w0.x + xv[i].y * w0.y + xv[i].z * w0.z + xv[i].w * w0.w;
            a1 += xv[i].x * w1.x + xv[i].y * w1.y + xv[i].z * w1.z + xv[i].w * w1.w;
            a2 += xv[i].x * w2.x + xv[i].y * w2.y + xv[i].z * w2.z + xv[i].w * w2.w;
        }
        #pragma unroll
        for (int off = 4; off; off >>= 1) {
            a0 += __shfl_xor_sync(FULLM, a0, off);
            a1 += __shfl_xor_sync(FULLM, a1, off);
            a2 += __shfl_xor_sync(FULLM, a2, off);
        }
        if (r == 0) {
            const float* gr = gu + (size_t)row * 3;
            float g0 = -logf(-logf(gr[0] + EPSF) + EPSF);
            float g1 = -logf(-logf(gr[1] + EPSF) + EPSF);
            float g2 = -logf(-logf(gr[2] + EPSF) + EPSF);
            float s0 = a0 + bias[0] + g0;
            float s1 = a1 + bias[1] + g1;
            float s2 = a2 + bias[2] + g2;
            int tt = 0; float best = s0;
            if (s1 > best) { best = s1; tt = 1; }   // first-max tie-break
            if (s2 > best) { best = s2; tt = 2; }
            g_tt[row] = tt;
        }
    }
    __syncthreads();
    if (tid == 0) {
        __threadfence();                              // release g_tt
        sh_last = (atomicAdd(&g_cnt, 1u) == TTBLK - 1);
    }
    __syncthreads();
    if (!sh_last) return;

    // ---------------- last block: suffix-min scan, publish (lo,hi) ----------
    __threadfence();                                  // acquire all g_tt
    int lane = tid & 31, wid = tid >> 5;              // 16 warps
    for (int b = 0; b < BB; b++) {
        __syncthreads();                              // shared reuse guard
        int base = b * SS + tid * 4;                  // 4 elems/thread
        int t0 = g_tt[base + 0], t1 = g_tt[base + 1];
        int t2 = g_tt[base + 2], t3 = g_tt[base + 3];
        int j0 = tid * 4;
        int e0 = (t0 == 0) ? j0     : SS;
        int e1 = (t1 == 0) ? j0 + 1 : SS;
        int e2 = (t2 == 0) ? j0 + 2 : SS;
        int e3 = (t3 == 0) ? j0 + 3 : SS;
        int m  = min(min(e0, e1), min(e2, e3));

        int inc = m;                                  // warp suffix-min (inclusive)
        #pragma unroll
        for (int off = 1; off < 32; off <<= 1) {
            int v = __shfl_down_sync(FULLM, inc, off);
            if (lane + off < 32) inc = min(inc, v);
        }
        int excl = __shfl_down_sync(FULLM, inc, 1);
        if (lane == 31) excl = SS;

        if (lane == 0) sh_wmin[wid] = inc;
        __syncthreads();
        if (wid == 0) {
            int wm = (lane < 16) ? sh_wmin[lane] : SS;
            int winc = wm;
            #pragma unroll
            for (int off = 1; off < 16; off <<= 1)
                winc = min(winc, __shfl_down_sync(FULLM, winc, off));
            int wex = __shfl_down_sync(FULLM, winc, 1);  // lane15 gets lane16's SS
            if (lane < 16) sh_wsuf[lane] = wex;
        }
        __syncthreads();
        int after = min(excl, sh_wsuf[wid]);          // min over idx > 4t+3

        int run = after;
        int ng3 = run; run = min(run, e3);
        int ng2 = run; run = min(run, e2);
        int ng1 = run; run = min(run, e1);
        int ng0 = run;

        int2 lh;
        #define EMIT(ii, tt_, ng_)                                  \
            { int j = j0 + ii; lh.x = 0; lh.y = j;                  \
              if (tt_ == 1)      { lh.x = j; lh.y = j; }            \
              else if (tt_ == 2) { lh.y = min(j, ng_); }            \
              g_lohi[base + ii] = lh; }
        EMIT(0, t0, ng0); EMIT(1, t1, ng1);
        EMIT(2, t2, ng2); EMIT(3, t3, ng3);
        #undef EMIT
    }
    __syncthreads();
    if (tid == 0) g_cnt = 0;            // reset for next graph replay
}

// ---------------------------------------------------------------------------
// Kernel P: causal prefixes for one complementary row pair: 513 float4s.
// ---------------------------------------------------------------------------
__global__ void __launch_bounds__(512) k_prefix(float4* __restrict__ out) {
    int pb = blockIdx.x;                 // 0..16383
    int bh = pb >> 10;
    int a  = pb & 1023;                  // s1 = a, s2 = 2047 - a
    int b  = bh >> 3;
    int c  = a >> 2;                     // qdiag row1; row2 qdiag = 511 - c

    int s2 = SS - 1 - a;
    int2 lh1 = g_lohi[b * SS + a];
    int2 lh2 = g_lohi[b * SS + s2];
    size_t base1 = (size_t)(bh * SS + a)  * QROW;
    size_t base2 = (size_t)(bh * SS + s2) * QROW;

    // 513 units: w in [0, c] -> row1 q=w ; w in (c, 513) -> row2 q=w-c-1
    for (int w = threadIdx.x; w < 513; w += 512) {
        int2 lh; size_t addr; int q;
        if (w <= c) { lh = lh1; q = w;         addr = base1 + q; }
        else        { lh = lh2; q = w - c - 1; addr = base2 + q; }
        int j = q << 2;
        float4 v;
        v.x = (j     >= lh.x && j     <= lh.y) ? 1.0f : 0.0f;
        v.y = (j + 1 >= lh.x && j + 1 <= lh.y) ? 1.0f : 0.0f;
        v.z = (j + 2 >= lh.x && j + 2 <= lh.y) ? 1.0f : 0.0f;
        v.w = (j + 3 >= lh.x && j + 3 <= lh.y) ? 1.0f : 0.0f;
        __stcs(&out[addr], v);
    }
}

extern "C" void kernel_launch(void* const* d_in, const int* in_sizes, int n_in,
                              void* d_out, int out_size) {
    const float* x    = (const float*)d_in[0];  // input_tensor (B,S,D)
    // d_in[1] = token_types (unused by reference)
    const float* gu   = (const float*)d_in[2];  // gumbel_u (B,S,3)
    const float* W    = (const float*)d_in[3];  // (3,D)
    const float* bias = (const float*)d_in[4];  // (3,)
    float4* out = (float4*)d_out;

    k_zero<<<TTBLK + NPAIR, 512>>>(x, gu, W, bias, out);
    k_prefix<<<NPAIR, 512>>>(out);
}

// round 8
// speedup vs baseline: 1.1463x; 1.0138x over previous
#include <cuda_runtime.h>

#define BB 2
#define SS 2048
#define DD 128
#define HH 8
#define EPSF 1e-10f
#define FULLM 0xffffffffu
#define TTBLK 64                 // phase-1 blocks (4096 rows, 8 thr/row, 512 thr/blk)
#define NPAIR (BB * HH * SS / 2) // 16384 complementary row pairs
#define QROW  (SS / 4)           // 512 float4 per row

// Scratch (allocation-free rule: __device__ globals; zero-init at load)
__device__ int      g_tt[BB * SS];
__device__ int2     g_lohi[BB * SS];
__device__ unsigned g_cnt = 0;

// ---------------------------------------------------------------------------
// Kernel Z: blocks 0..63 = phase-1 (tt + suffix-min scan -> g_lohi).
//           blocks 64..  = suffix zeros for one complementary row pair
//                          (s, 2047-s): exactly 511 float4s, all threads busy.
// ---------------------------------------------------------------------------
__global__ void __launch_bounds__(512) k_zero(const float* __restrict__ x,
                                              const float* __restrict__ gu,
                                              const float* __restrict__ W,
                                              const float* __restrict__ bias,
                                              float4* __restrict__ out) {
    const int tid = threadIdx.x;
    const int bid = blockIdx.x;

    if (bid >= TTBLK) {
        // ---------------- balanced suffix-zero writer ----------------
        int zb = bid - TTBLK;            // 0..16383
        int bh = zb >> 10;               // (b*8 + h)
        int a  = zb & 1023;              // s1 = a, s2 = 2047 - a
        int c  = a >> 2;                 // qdiag of row1; qdiag2 = 511 - c
        size_t base1 = (size_t)(bh * SS + a)        * QROW;
        size_t base2 = (size_t)(bh * SS + (SS-1-a)) * QROW;
        float4 z = make_float4(0.f, 0.f, 0.f, 0.f);
        int nz1 = 511 - c;               // zero float4s in row1
        if (tid < 511) {
            if (tid < nz1) __stcs(&out[base1 + c + 1 + tid], z);
            else           __stcs(&out[base2 + tid + 1], z);
        }
        return;
    }

    // ---------------- phase-1: token types ----------------
    __shared__ int sh_last;
    __shared__ int sh_wmin[16];
    __shared__ int sh_wsuf[16];

    {
        int gid = bid * 512 + tid;
        int row = gid >> 3;              // 0..4095 = b*S + s
        int r   = gid & 7;

        const float4* xr = reinterpret_cast<const float4*>(x + (size_t)row * DD);
        const float4* W4 = reinterpret_cast<const float4*>(W);

        float4 xv[4];
        #pragma unroll
        for (int i = 0; i < 4; i++) xv[i] = xr[r * 4 + i];

        float a0 = 0.f, a1 = 0.f, a2 = 0.f;
        #pragma unroll
        for (int i = 0; i < 4; i++) {
            int cc = r * 4 + i;
            float4 w0 = W4[cc];
            float4 w1 = W4[32 + cc];
            float4 w2 = W4[64 + cc];
            a0 += xv[i].x * w0.x + xv[i].y * w0.y + xv[i].z * w0.z + xv[i].w * w0.w;
            a1 += xv[i].x * w1.x + xv[i].y * w1.y + xv[i].z * w1.z + xv[i].w * w1.w;
            a2 += xv[i].x * w2.x + xv[i].y * w2.y + xv[i].z * w2.z + xv[i].w * w2.w;
        }
        #pragma unroll
        for (int off = 4; off; off >>= 1) {
            a0 += __shfl_xor_sync(FULLM, a0, off);
            a1 += __shfl_xor_sync(FULLM, a1, off);
            a2 += __shfl_xor_sync(FULLM, a2, off);
        }
        if (r == 0) {
            const float* gr = gu + (size_t)row * 3;
            float g0 = -logf(-logf(gr[0] + EPSF) + EPSF);
            float g1 = -logf(-logf(gr[1] + EPSF) + EPSF);
            float g2 = -logf(-logf(gr[2] + EPSF) + EPSF);
            float s0 = a0 + bias[0] + g0;
            float s1 = a1 + bias[1] + g1;
            float s2 = a2 + bias[2] + g2;
            int tt = 0; float best = s0;
            if (s1 > best) { best = s1; tt = 1; }   // first-max tie-break
            if (s2 > best) { best = s2; tt = 2; }
            g_tt[row] = tt;
        }
    }
    __syncthreads();
    if (tid == 0) {
        __threadfence();                              // release g_tt
        sh_last = (atomicAdd(&g_cnt, 1u) == TTBLK - 1);
    }
    __syncthreads();
    if (!sh_last) return;

    // ---------------- last block: suffix-min scan, publish (lo,hi) ----------
    __threadfence();                                  // acquire all g_tt
    int lane = tid & 31, wid = tid >> 5;              // 16 warps
    for (int b = 0; b < BB; b++) {
        __syncthreads();                              // shared reuse guard
        int base = b * SS + tid * 4;                  // 4 elems/thread
        int t0 = g_tt[base + 0], t1 = g_tt[base + 1];
        int t2 = g_tt[base + 2], t3 = g_tt[base + 3];
        int j0 = tid * 4;
        int e0 = (t0 == 0) ? j0     : SS;
        int e1 = (t1 == 0) ? j0 + 1 : SS;
        int e2 = (t2 == 0) ? j0 + 2 : SS;
        int e3 = (t3 == 0) ? j0 + 3 : SS;
        int m  = min(min(e0, e1), min(e2, e3));

        int inc = m;                                  // warp suffix-min (inclusive)
        #pragma unroll
        for (int off = 1; off < 32; off <<= 1) {
            int v = __shfl_down_sync(FULLM, inc, off);
            if (lane + off < 32) inc = min(inc, v);
        }
        int excl = __shfl_down_sync(FULLM, inc, 1);
        if (lane == 31) excl = SS;

        if (lane == 0) sh_wmin[wid] = inc;
        __syncthreads();
        if (wid == 0) {
            int wm = (lane < 16) ? sh_wmin[lane] : SS;
            int winc = wm;
            #pragma unroll
            for (int off = 1; off < 16; off <<= 1)
                winc = min(winc, __shfl_down_sync(FULLM, winc, off));
            int wex = __shfl_down_sync(FULLM, winc, 1);  // lane15 gets lane16's SS
            if (lane < 16) sh_wsuf[lane] = wex;
        }
        __syncthreads();
        int after = min(excl, sh_wsuf[wid]);          // min over idx > 4t+3

        int run = after;
        int ng3 = run; run = min(run, e3);
        int ng2 = run; run = min(run, e2);
        int ng1 = run; run = min(run, e1);
        int ng0 = run;

        int2 lh;
        #define EMIT(ii, tt_, ng_)                                  \
            { int j = j0 + ii; lh.x = 0; lh.y = j;                  \
              if (tt_ == 1)      { lh.x = j; lh.y = j; }            \
              else if (tt_ == 2) { lh.y = min(j, ng_); }            \
              g_lohi[base + ii] = lh; }
        EMIT(0, t0, ng0); EMIT(1, t1, ng1);
        EMIT(2, t2, ng2); EMIT(3, t3, ng3);
        #undef EMIT
    }
    __syncthreads();
    if (tid == 0) g_cnt = 0;            // reset for next graph replay
}

// ---------------------------------------------------------------------------
// Quad store: fast constant path (all-ones / all-zero), rare mixed boundary.
// ---------------------------------------------------------------------------
__device__ __forceinline__ void store_quad(float4* p, int q, int lo, int hi) {
    int j = q << 2;
    float4 v;
    if (j >= lo && j + 3 <= hi) {
        v = make_float4(1.f, 1.f, 1.f, 1.f);
    } else if (j + 3 < lo || j > hi) {
        v = make_float4(0.f, 0.f, 0.f, 0.f);
    } else {
        v.x = (j     >= lo && j     <= hi) ? 1.f : 0.f;
        v.y = (j + 1 >= lo && j + 1 <= hi) ? 1.f : 0.f;
        v.z = (j + 2 >= lo && j + 2 <= hi) ? 1.f : 0.f;
        v.w = (j + 3 >= lo && j + 3 <= hi) ? 1.f : 0.f;
    }
    __stcs(p, v);
}

// ---------------------------------------------------------------------------
// Kernel P: causal prefixes for one complementary row pair: 513 float4s.
// One predicated LDG + one (rarely two) constant stores per thread.
// ---------------------------------------------------------------------------
__global__ void __launch_bounds__(512) k_prefix(float4* __restrict__ out) {
    int pb = blockIdx.x;                 // 0..16383
    int bh = pb >> 10;
    int a  = pb & 1023;                  // s1 = a, s2 = 2047 - a
    int b  = bh >> 3;
    int c  = a >> 2;                     // qdiag row1; row2 qdiag = 511 - c
    int s2 = SS - 1 - a;
    int tid = threadIdx.x;

    bool r1  = (tid <= c);
    int srow = r1 ? a : s2;
    int q    = r1 ? tid : tid - c;       // row1 q=0..c ; row2 q=1..511-c
    int2 lh  = g_lohi[b * SS + srow];    // single load per thread
    size_t base = (size_t)(bh * SS + srow) * QROW;
    store_quad(&out[base + q], q, lh.x, lh.y);

    if (tid == c) {                      // row2 q=0 (the one uncovered unit)
        int2 lh2 = g_lohi[b * SS + s2];
        store_quad(&out[(size_t)(bh * SS + s2) * QROW], 0, lh2.x, lh2.y);
    }
}

extern "C" void kernel_launch(void* const* d_in, const int* in_sizes, int n_in,
                              void* d_out, int out_size) {
    const float* x    = (const float*)d_in[0];  // input_tensor (B,S,D)
    // d_in[1] = token_types (unused by reference)
    const float* gu   = (const float*)d_in[2];  // gumbel_u (B,S,3)
    const float* W    = (const float*)d_in[3];  // (3,D)
    const float* bias = (const float*)d_in[4];  // (3,)
    float4* out = (float4*)d_out;

    k_zero<<<TTBLK + NPAIR, 512>>>(x, gu, W, bias, out);
    k_prefix<<<NPAIR, 512>>>(out);
}